// round 2
// baseline (speedup 1.0000x reference)
#include <cuda_runtime.h>
#include <cstdint>

#define B_DIM 4096
#define N_CIT 16
#define D_IN  1024
#define D_OUT 1024
#define EPSV  0.01f

// ---------------- scratch (static device allocations; no cudaMalloc) --------
__device__ float g_logits[B_DIM * N_CIT * N_CIT];   // [B, 256]  (pre-softmax, bd added)
__device__ float g_power [B_DIM * N_CIT];           // [B, 16]

// ---------------- f32x2 helpers ---------------------------------------------
__device__ __forceinline__ void ffma2(unsigned long long& d, unsigned long long a,
                                      unsigned long long b) {
    asm("fma.rn.f32x2 %0, %1, %2, %0;" : "+l"(d) : "l"(a), "l"(b));
}
__device__ __forceinline__ unsigned long long pack2(float lo, float hi) {
    unsigned long long r;
    asm("mov.b64 %0, {%1, %2};" : "=l"(r) : "f"(lo), "f"(hi));
    return r;
}
__device__ __forceinline__ float2 unpack2(unsigned long long v) {
    float2 r;
    asm("mov.b64 {%0, %1}, %2;" : "=f"(r.x), "=f"(r.y) : "l"(v));
    return r;
}

// ============================================================================
// Kernel 1: logits[b, c] = sum_i x[b,i] * Wd[n,i,j] + bd[n,j],  c = n*16+j
// 64x64 tile GEMM over [4096, 256], K=1024
// ============================================================================
__global__ __launch_bounds__(256) void logits_kernel(
    const float* __restrict__ x, const float* __restrict__ Wd,
    const float* __restrict__ bd)
{
    __shared__ float Xs[32][68];   // [k][m], padded for alignment
    __shared__ float Ws[32][64];   // [k][c]

    const int bm = blockIdx.y * 64;
    const int bc = blockIdx.x * 64;
    const int tid = threadIdx.x;
    const int tx = tid & 15, ty = tid >> 4;

    float acc[4][4] = {};

    for (int k0 = 0; k0 < D_IN; k0 += 32) {
        // load X tile: 64 rows x 32 k
        #pragma unroll
        for (int j = 0; j < 2; j++) {
            int L = tid + j * 256;          // 0..511
            int m = L >> 3, kq = L & 7;
            float4 v = *(const float4*)&x[(size_t)(bm + m) * D_IN + k0 + kq * 4];
            Xs[kq * 4 + 0][m] = v.x;
            Xs[kq * 4 + 1][m] = v.y;
            Xs[kq * 4 + 2][m] = v.z;
            Xs[kq * 4 + 3][m] = v.w;
        }
        // load Wd tile: 32 k x 64 c, c = n*16 + j  -> Wd[n*16384 + k*16 + j]
        #pragma unroll
        for (int j = 0; j < 2; j++) {
            int L = tid + j * 256;          // 0..511
            int kk = L >> 4, c4 = L & 15;
            int c = bc + c4 * 4;
            int n = c >> 4, jj = c & 15;
            float4 v = *(const float4*)&Wd[(size_t)n * (D_IN * N_CIT) + (size_t)(k0 + kk) * N_CIT + jj];
            *(float4*)&Ws[kk][c4 * 4] = v;
        }
        __syncthreads();
        #pragma unroll
        for (int kk = 0; kk < 32; kk++) {
            float4 a4 = *(const float4*)&Xs[kk][ty * 4];
            float4 b4 = *(const float4*)&Ws[kk][tx * 4];
            float a[4] = {a4.x, a4.y, a4.z, a4.w};
            float b[4] = {b4.x, b4.y, b4.z, b4.w};
            #pragma unroll
            for (int mi = 0; mi < 4; mi++)
                #pragma unroll
                for (int ci = 0; ci < 4; ci++)
                    acc[mi][ci] += a[mi] * b[ci];
        }
        __syncthreads();
    }

    // write logits + bd  (bd is [16,16] contiguous -> bd[c])
    const int cg = bc + tx * 4;
    #pragma unroll
    for (int mi = 0; mi < 4; mi++) {
        int m = bm + ty * 4 + mi;
        float4 r;
        r.x = acc[mi][0] + bd[cg + 0];
        r.y = acc[mi][1] + bd[cg + 1];
        r.z = acc[mi][2] + bd[cg + 2];
        r.w = acc[mi][3] + bd[cg + 3];
        *(float4*)&g_logits[(size_t)m * 256 + cg] = r;
    }
}

// ============================================================================
// Kernel 2: per-batch softmax + 16x16 linear solve -> power[b, 16]
//   M16[r][i] = (i==r) ? 1 : -(1-eps)*dall[i*16+r];  solve M16 z = 1
//   z16 = 1 + eps * sum(z)
//   power[j] = z[j]*(1-eps)*dall[j*16+j] + z16/16 - 1/16
// ============================================================================
__global__ __launch_bounds__(256) void power_kernel()
{
    int b = blockIdx.x * blockDim.x + threadIdx.x;
    if (b >= B_DIM) return;
    const float* lg = g_logits + (size_t)b * 256;

    float dl[256];
    for (int n = 0; n < N_CIT; n++) {
        float mx = lg[n * 16];
        for (int j = 1; j < 16; j++) mx = fmaxf(mx, lg[n * 16 + j]);
        float s = 0.f;
        for (int j = 0; j < 16; j++) {
            float e = expf(lg[n * 16 + j] - mx);
            dl[n * 16 + j] = e;
            s += e;
        }
        float inv = 1.f / s;
        for (int j = 0; j < 16; j++) dl[n * 16 + j] *= inv;
    }

    const float ome = 1.f - EPSV;
    float A[16][17];
    for (int r = 0; r < 16; r++) {
        for (int i = 0; i < 16; i++)
            A[r][i] = (i == r) ? 1.f : -ome * dl[i * 16 + r];
        A[r][16] = 1.f;
    }
    // Gaussian elimination (column-diagonally-dominant -> no pivoting needed)
    for (int p = 0; p < 16; p++) {
        float inv = 1.f / A[p][p];
        for (int c = p; c < 17; c++) A[p][c] *= inv;
        for (int r = p + 1; r < 16; r++) {
            float f = A[r][p];
            for (int c = p; c < 17; c++) A[r][c] -= f * A[p][c];
        }
    }
    float z[16];
    for (int r = 15; r >= 0; r--) {
        float s = A[r][16];
        for (int c = r + 1; c < 16; c++) s -= A[r][c] * z[c];
        z[r] = s;
    }
    float zs = 0.f;
    for (int i = 0; i < 16; i++) zs += z[i];
    float z16 = 1.f + EPSV * zs;
    float add = z16 * (1.f / 16.f) - (1.f / 16.f);
    for (int j = 0; j < 16; j++)
        g_power[(size_t)b * 16 + j] = z[j] * ome * dl[j * 16 + j] + add;
}

// ============================================================================
// Kernel 3: y[b,o] = sum_{k=0..16383} (power[b, k>>10] * x[b, k&1023]) * WyF[k, o]
//                  + sum_n power[b,n] * by[n, o]
// 128x128x16 tiles, 256 threads, 8x8 microtiles with packed f32x2 FMA.
// ============================================================================
__global__ __launch_bounds__(256, 1) void main_gemm(
    const float* __restrict__ x, const float* __restrict__ Wy,
    const float* __restrict__ by, float* __restrict__ out)
{
    __shared__ float As[16][128];   // [k][m], A = power-scaled x
    __shared__ float Bs[16][128];   // [k][o]
    __shared__ float Ps[128][17];   // power rows for this block (padded)

    const int bm = blockIdx.y * 128;
    const int bn = blockIdx.x * 128;
    const int tid = threadIdx.x;
    const int tx = tid & 15, ty = tid >> 4;

    // preload power rows
    #pragma unroll
    for (int j = 0; j < 8; j++) {
        int L = tid + j * 256;            // 0..2047
        int m = L >> 4, q = L & 15;
        Ps[m][q] = g_power[(size_t)(bm + m) * 16 + q];
    }
    __syncthreads();

    unsigned long long acc[8][4];
    #pragma unroll
    for (int mi = 0; mi < 8; mi++)
        #pragma unroll
        for (int cj = 0; cj < 4; cj++) acc[mi][cj] = 0ull;   // two packed +0.0f

    for (int k0 = 0; k0 < N_CIT * D_IN; k0 += 16) {
        const int n = k0 >> 10;
        const int ki = k0 & 1023;
        // A tile: generate power[b,n]*x[b,i]
        #pragma unroll
        for (int j = 0; j < 2; j++) {
            int L = tid + j * 256;        // 0..511
            int m = L & 127, kq = L >> 7; // kq 0..3
            float4 v = *(const float4*)&x[(size_t)(bm + m) * D_IN + ki + kq * 4];
            float p = Ps[m][n];
            As[kq * 4 + 0][m] = v.x * p;
            As[kq * 4 + 1][m] = v.y * p;
            As[kq * 4 + 2][m] = v.z * p;
            As[kq * 4 + 3][m] = v.w * p;
        }
        // B tile: Wy flattened [16384, 1024]
        #pragma unroll
        for (int j = 0; j < 2; j++) {
            int L = tid + j * 256;        // 0..511
            int kk = L >> 5, c4 = L & 31;
            *(float4*)&Bs[kk][c4 * 4] =
                *(const float4*)&Wy[(size_t)(k0 + kk) * D_OUT + bn + c4 * 4];
        }
        __syncthreads();
        #pragma unroll
        for (int kk = 0; kk < 16; kk++) {
            float4 a0 = *(const float4*)&As[kk][ty * 8];
            float4 a1 = *(const float4*)&As[kk][ty * 8 + 4];
            float4 b0 = *(const float4*)&Bs[kk][tx * 8];
            float4 b1 = *(const float4*)&Bs[kk][tx * 8 + 4];
            unsigned long long bp[4];
            bp[0] = pack2(b0.x, b0.y);
            bp[1] = pack2(b0.z, b0.w);
            bp[2] = pack2(b1.x, b1.y);
            bp[3] = pack2(b1.z, b1.w);
            float av[8] = {a0.x, a0.y, a0.z, a0.w, a1.x, a1.y, a1.z, a1.w};
            #pragma unroll
            for (int mi = 0; mi < 8; mi++) {
                unsigned long long ap = pack2(av[mi], av[mi]);
                #pragma unroll
                for (int cj = 0; cj < 4; cj++)
                    ffma2(acc[mi][cj], ap, bp[cj]);
            }
        }
        __syncthreads();
    }

    // unpack accumulators
    float accf[8][8];
    #pragma unroll
    for (int mi = 0; mi < 8; mi++)
        #pragma unroll
        for (int cj = 0; cj < 4; cj++) {
            float2 v = unpack2(acc[mi][cj]);
            accf[mi][cj * 2 + 0] = v.x;
            accf[mi][cj * 2 + 1] = v.y;
        }

    // bias term: + sum_n Ps[m][n] * by[n, c]
    #pragma unroll
    for (int n = 0; n < N_CIT; n++) {
        float4 u0 = *(const float4*)&by[(size_t)n * D_OUT + bn + tx * 8];
        float4 u1 = *(const float4*)&by[(size_t)n * D_OUT + bn + tx * 8 + 4];
        float bc[8] = {u0.x, u0.y, u0.z, u0.w, u1.x, u1.y, u1.z, u1.w};
        #pragma unroll
        for (int mi = 0; mi < 8; mi++) {
            float p = Ps[ty * 8 + mi][n];
            #pragma unroll
            for (int c = 0; c < 8; c++) accf[mi][c] += p * bc[c];
        }
    }

    // write out
    #pragma unroll
    for (int mi = 0; mi < 8; mi++) {
        int m = bm + ty * 8 + mi;
        float4 o0 = make_float4(accf[mi][0], accf[mi][1], accf[mi][2], accf[mi][3]);
        float4 o1 = make_float4(accf[mi][4], accf[mi][5], accf[mi][6], accf[mi][7]);
        *(float4*)&out[(size_t)m * D_OUT + bn + tx * 8] = o0;
        *(float4*)&out[(size_t)m * D_OUT + bn + tx * 8 + 4] = o1;
    }
}

// ============================================================================
extern "C" void kernel_launch(void* const* d_in, const int* in_sizes, int n_in,
                              void* d_out, int out_size)
{
    const float* x  = (const float*)d_in[0];
    const float* Wy = (const float*)d_in[1];
    const float* by = (const float*)d_in[2];
    const float* Wd = (const float*)d_in[3];
    const float* bd = (const float*)d_in[4];
    float* out = (float*)d_out;

    logits_kernel<<<dim3(256 / 64, B_DIM / 64), 256>>>(x, Wd, bd);
    power_kernel<<<B_DIM / 256, 256>>>();
    main_gemm<<<dim3(D_OUT / 128, B_DIM / 128), 256>>>(x, Wy, by, out);
}

// round 3
// speedup vs baseline: 1.0003x; 1.0003x over previous
#include <cuda_runtime.h>
#include <cstdint>

#define B_DIM 4096
#define N_CIT 16
#define D_IN  1024
#define D_OUT 1024
#define EPSV  0.01f

// ---------------- scratch (static device allocations; no cudaMalloc) --------
__device__ float g_logits[B_DIM * N_CIT * N_CIT];   // [B, 256]  (pre-softmax, bd added)
__device__ float g_power [B_DIM * N_CIT];           // [B, 16]

// ---------------- f32x2 helpers ---------------------------------------------
__device__ __forceinline__ void ffma2(unsigned long long& d, unsigned long long a,
                                      unsigned long long b) {
    asm("fma.rn.f32x2 %0, %1, %2, %0;" : "+l"(d) : "l"(a), "l"(b));
}
__device__ __forceinline__ unsigned long long pack2(float lo, float hi) {
    unsigned long long r;
    asm("mov.b64 %0, {%1, %2};" : "=l"(r) : "f"(lo), "f"(hi));
    return r;
}
__device__ __forceinline__ float2 unpack2(unsigned long long v) {
    float2 r;
    asm("mov.b64 {%0, %1}, %2;" : "=f"(r.x), "=f"(r.y) : "l"(v));
    return r;
}

// ============================================================================
// Kernel 1: logits[b, c] = sum_i x[b,i] * Wd[n,i,j] + bd[n,j],  c = n*16+j
// 64x64 tile GEMM over [4096, 256], K=1024
// ============================================================================
__global__ __launch_bounds__(256) void logits_kernel(
    const float* __restrict__ x, const float* __restrict__ Wd,
    const float* __restrict__ bd)
{
    __shared__ float Xs[32][68];   // [k][m], padded for alignment
    __shared__ float Ws[32][64];   // [k][c]

    const int bm = blockIdx.y * 64;
    const int bc = blockIdx.x * 64;
    const int tid = threadIdx.x;
    const int tx = tid & 15, ty = tid >> 4;

    float acc[4][4] = {};

    for (int k0 = 0; k0 < D_IN; k0 += 32) {
        // load X tile: 64 rows x 32 k
        #pragma unroll
        for (int j = 0; j < 2; j++) {
            int L = tid + j * 256;          // 0..511
            int m = L >> 3, kq = L & 7;
            float4 v = *(const float4*)&x[(size_t)(bm + m) * D_IN + k0 + kq * 4];
            Xs[kq * 4 + 0][m] = v.x;
            Xs[kq * 4 + 1][m] = v.y;
            Xs[kq * 4 + 2][m] = v.z;
            Xs[kq * 4 + 3][m] = v.w;
        }
        // load Wd tile: 32 k x 64 c, c = n*16 + j  -> Wd[n*16384 + k*16 + j]
        #pragma unroll
        for (int j = 0; j < 2; j++) {
            int L = tid + j * 256;          // 0..511
            int kk = L >> 4, c4 = L & 15;
            int c = bc + c4 * 4;
            int n = c >> 4, jj = c & 15;
            float4 v = *(const float4*)&Wd[(size_t)n * (D_IN * N_CIT) + (size_t)(k0 + kk) * N_CIT + jj];
            *(float4*)&Ws[kk][c4 * 4] = v;
        }
        __syncthreads();
        #pragma unroll
        for (int kk = 0; kk < 32; kk++) {
            float4 a4 = *(const float4*)&Xs[kk][ty * 4];
            float4 b4 = *(const float4*)&Ws[kk][tx * 4];
            float a[4] = {a4.x, a4.y, a4.z, a4.w};
            float b[4] = {b4.x, b4.y, b4.z, b4.w};
            #pragma unroll
            for (int mi = 0; mi < 4; mi++)
                #pragma unroll
                for (int ci = 0; ci < 4; ci++)
                    acc[mi][ci] += a[mi] * b[ci];
        }
        __syncthreads();
    }

    // write logits + bd  (bd is [16,16] contiguous -> bd[c])
    const int cg = bc + tx * 4;
    #pragma unroll
    for (int mi = 0; mi < 4; mi++) {
        int m = bm + ty * 4 + mi;
        float4 r;
        r.x = acc[mi][0] + bd[cg + 0];
        r.y = acc[mi][1] + bd[cg + 1];
        r.z = acc[mi][2] + bd[cg + 2];
        r.w = acc[mi][3] + bd[cg + 3];
        *(float4*)&g_logits[(size_t)m * 256 + cg] = r;
    }
}

// ============================================================================
// Kernel 2: per-batch softmax + 16x16 linear solve -> power[b, 16]
//   M16[r][i] = (i==r) ? 1 : -(1-eps)*dall[i*16+r];  solve M16 z = 1
//   z16 = 1 + eps * sum(z)
//   power[j] = z[j]*(1-eps)*dall[j*16+j] + z16/16 - 1/16
// ============================================================================
__global__ __launch_bounds__(256) void power_kernel()
{
    int b = blockIdx.x * blockDim.x + threadIdx.x;
    if (b >= B_DIM) return;
    const float* lg = g_logits + (size_t)b * 256;

    float dl[256];
    for (int n = 0; n < N_CIT; n++) {
        float mx = lg[n * 16];
        for (int j = 1; j < 16; j++) mx = fmaxf(mx, lg[n * 16 + j]);
        float s = 0.f;
        for (int j = 0; j < 16; j++) {
            float e = expf(lg[n * 16 + j] - mx);
            dl[n * 16 + j] = e;
            s += e;
        }
        float inv = 1.f / s;
        for (int j = 0; j < 16; j++) dl[n * 16 + j] *= inv;
    }

    const float ome = 1.f - EPSV;
    float A[16][17];
    for (int r = 0; r < 16; r++) {
        for (int i = 0; i < 16; i++)
            A[r][i] = (i == r) ? 1.f : -ome * dl[i * 16 + r];
        A[r][16] = 1.f;
    }
    // Gaussian elimination (column-diagonally-dominant -> no pivoting needed)
    for (int p = 0; p < 16; p++) {
        float inv = 1.f / A[p][p];
        for (int c = p; c < 17; c++) A[p][c] *= inv;
        for (int r = p + 1; r < 16; r++) {
            float f = A[r][p];
            for (int c = p; c < 17; c++) A[r][c] -= f * A[p][c];
        }
    }
    float z[16];
    for (int r = 15; r >= 0; r--) {
        float s = A[r][16];
        for (int c = r + 1; c < 16; c++) s -= A[r][c] * z[c];
        z[r] = s;
    }
    float zs = 0.f;
    for (int i = 0; i < 16; i++) zs += z[i];
    float z16 = 1.f + EPSV * zs;
    float add = z16 * (1.f / 16.f) - (1.f / 16.f);
    for (int j = 0; j < 16; j++)
        g_power[(size_t)b * 16 + j] = z[j] * ome * dl[j * 16 + j] + add;
}

// ============================================================================
// Kernel 3: y[b,o] = sum_{k=0..16383} (power[b, k>>10] * x[b, k&1023]) * WyF[k, o]
//                  + sum_n power[b,n] * by[n, o]
// 128x128x16 tiles, 256 threads, 8x8 microtiles with packed f32x2 FMA.
// ============================================================================
__global__ __launch_bounds__(256, 1) void main_gemm(
    const float* __restrict__ x, const float* __restrict__ Wy,
    const float* __restrict__ by, float* __restrict__ out)
{
    __shared__ float As[16][128];   // [k][m], A = power-scaled x
    __shared__ float Bs[16][128];   // [k][o]
    __shared__ float Ps[128][17];   // power rows for this block (padded)

    const int bm = blockIdx.y * 128;
    const int bn = blockIdx.x * 128;
    const int tid = threadIdx.x;
    const int tx = tid & 15, ty = tid >> 4;

    // preload power rows
    #pragma unroll
    for (int j = 0; j < 8; j++) {
        int L = tid + j * 256;            // 0..2047
        int m = L >> 4, q = L & 15;
        Ps[m][q] = g_power[(size_t)(bm + m) * 16 + q];
    }
    __syncthreads();

    unsigned long long acc[8][4];
    #pragma unroll
    for (int mi = 0; mi < 8; mi++)
        #pragma unroll
        for (int cj = 0; cj < 4; cj++) acc[mi][cj] = 0ull;   // two packed +0.0f

    for (int k0 = 0; k0 < N_CIT * D_IN; k0 += 16) {
        const int n = k0 >> 10;
        const int ki = k0 & 1023;
        // A tile: generate power[b,n]*x[b,i]
        #pragma unroll
        for (int j = 0; j < 2; j++) {
            int L = tid + j * 256;        // 0..511
            int m = L & 127, kq = L >> 7; // kq 0..3
            float4 v = *(const float4*)&x[(size_t)(bm + m) * D_IN + ki + kq * 4];
            float p = Ps[m][n];
            As[kq * 4 + 0][m] = v.x * p;
            As[kq * 4 + 1][m] = v.y * p;
            As[kq * 4 + 2][m] = v.z * p;
            As[kq * 4 + 3][m] = v.w * p;
        }
        // B tile: Wy flattened [16384, 1024]
        #pragma unroll
        for (int j = 0; j < 2; j++) {
            int L = tid + j * 256;        // 0..511
            int kk = L >> 5, c4 = L & 31;
            *(float4*)&Bs[kk][c4 * 4] =
                *(const float4*)&Wy[(size_t)(k0 + kk) * D_OUT + bn + c4 * 4];
        }
        __syncthreads();
        #pragma unroll
        for (int kk = 0; kk < 16; kk++) {
            float4 a0 = *(const float4*)&As[kk][ty * 8];
            float4 a1 = *(const float4*)&As[kk][ty * 8 + 4];
            float4 b0 = *(const float4*)&Bs[kk][tx * 8];
            float4 b1 = *(const float4*)&Bs[kk][tx * 8 + 4];
            unsigned long long bp[4];
            bp[0] = pack2(b0.x, b0.y);
            bp[1] = pack2(b0.z, b0.w);
            bp[2] = pack2(b1.x, b1.y);
            bp[3] = pack2(b1.z, b1.w);
            float av[8] = {a0.x, a0.y, a0.z, a0.w, a1.x, a1.y, a1.z, a1.w};
            #pragma unroll
            for (int mi = 0; mi < 8; mi++) {
                unsigned long long ap = pack2(av[mi], av[mi]);
                #pragma unroll
                for (int cj = 0; cj < 4; cj++)
                    ffma2(acc[mi][cj], ap, bp[cj]);
            }
        }
        __syncthreads();
    }

    // unpack accumulators
    float accf[8][8];
    #pragma unroll
    for (int mi = 0; mi < 8; mi++)
        #pragma unroll
        for (int cj = 0; cj < 4; cj++) {
            float2 v = unpack2(acc[mi][cj]);
            accf[mi][cj * 2 + 0] = v.x;
            accf[mi][cj * 2 + 1] = v.y;
        }

    // bias term: + sum_n Ps[m][n] * by[n, c]
    #pragma unroll
    for (int n = 0; n < N_CIT; n++) {
        float4 u0 = *(const float4*)&by[(size_t)n * D_OUT + bn + tx * 8];
        float4 u1 = *(const float4*)&by[(size_t)n * D_OUT + bn + tx * 8 + 4];
        float bc[8] = {u0.x, u0.y, u0.z, u0.w, u1.x, u1.y, u1.z, u1.w};
        #pragma unroll
        for (int mi = 0; mi < 8; mi++) {
            float p = Ps[ty * 8 + mi][n];
            #pragma unroll
            for (int c = 0; c < 8; c++) accf[mi][c] += p * bc[c];
        }
    }

    // write out
    #pragma unroll
    for (int mi = 0; mi < 8; mi++) {
        int m = bm + ty * 8 + mi;
        float4 o0 = make_float4(accf[mi][0], accf[mi][1], accf[mi][2], accf[mi][3]);
        float4 o1 = make_float4(accf[mi][4], accf[mi][5], accf[mi][6], accf[mi][7]);
        *(float4*)&out[(size_t)m * D_OUT + bn + tx * 8] = o0;
        *(float4*)&out[(size_t)m * D_OUT + bn + tx * 8 + 4] = o1;
    }
}

// ============================================================================
extern "C" void kernel_launch(void* const* d_in, const int* in_sizes, int n_in,
                              void* d_out, int out_size)
{
    const float* x  = (const float*)d_in[0];
    const float* Wy = (const float*)d_in[1];
    const float* by = (const float*)d_in[2];
    const float* Wd = (const float*)d_in[3];
    const float* bd = (const float*)d_in[4];
    float* out = (float*)d_out;

    logits_kernel<<<dim3(256 / 64, B_DIM / 64), 256>>>(x, Wd, bd);
    power_kernel<<<B_DIM / 256, 256>>>();
    main_gemm<<<dim3(D_OUT / 128, B_DIM / 128), 256>>>(x, Wy, by, out);
}

// round 5
// speedup vs baseline: 2.4693x; 2.4685x over previous
#include <cuda_runtime.h>
#include <cuda_bf16.h>
#include <cstdint>

#define B_DIM 4096
#define N_CIT 16
#define D_IN  1024
#define D_OUT 1024
#define KTOT  (N_CIT * D_IN)       /* 16384 */
#define EPSV  0.01f

// ---------------- scratch (static device arrays; no cudaMalloc) -------------
__device__ float g_logits[B_DIM * 256];
__device__ float g_power [B_DIM * 16];
__device__ __nv_bfloat16 g_wt_hi[(size_t)D_OUT * KTOT];  // [o][k] K-major
__device__ __nv_bfloat16 g_wt_lo[(size_t)D_OUT * KTOT];
__device__ __nv_bfloat16 g_by_hi[(size_t)D_OUT * 32];    // [o][k] k=0..15 real, 16..31 zero
__device__ __nv_bfloat16 g_by_lo[(size_t)D_OUT * 32];

// ---------------- helpers ----------------------------------------------------
__device__ __forceinline__ uint32_t smem_to_u32(const void* p) {
    uint32_t a;
    asm("{ .reg .u64 t; cvta.to.shared.u64 t, %1; cvt.u32.u64 %0, t; }" : "=r"(a) : "l"(p));
    return a;
}

// swizzled address inside a tile of 64B rows: granule q (0..3) of row
__device__ __forceinline__ uint32_t sw(uint32_t base, int row, int q) {
    return base + row * 64 + (((uint32_t)(q ^ ((row >> 1) & 3))) << 4);
}

// pack two floats as bf16x2 (f0 -> low half)
__device__ __forceinline__ uint32_t pack_bf16(float f0, float f1) {
    uint32_t r;
    asm("cvt.rn.bf16x2.f32 %0, %1, %2;" : "=r"(r) : "f"(f1), "f"(f0));
    return r;
}

#define CP_ASYNC16(dst, src) \
    asm volatile("cp.async.cg.shared.global [%0], [%1], 16;" :: "r"(dst), "l"(src) : "memory")
#define CP_COMMIT() asm volatile("cp.async.commit_group;" ::: "memory")
#define CP_WAIT1()  asm volatile("cp.async.wait_group 1;" ::: "memory")
#define CP_WAIT0()  asm volatile("cp.async.wait_group 0;" ::: "memory")

#define LDSM4(r, addr) \
    asm volatile("ldmatrix.sync.aligned.m8n8.x4.shared.b16 {%0,%1,%2,%3}, [%4];" \
        : "=r"((r)[0]), "=r"((r)[1]), "=r"((r)[2]), "=r"((r)[3]) : "r"(addr))

#define MMA_BF16(d, a, b) \
    asm volatile("mma.sync.aligned.m16n8k16.row.col.f32.bf16.bf16.f32 " \
        "{%0,%1,%2,%3}, {%4,%5,%6,%7}, {%8,%9}, {%0,%1,%2,%3};" \
        : "+f"((d)[0]), "+f"((d)[1]), "+f"((d)[2]), "+f"((d)[3]) \
        : "r"((a)[0]), "r"((a)[1]), "r"((a)[2]), "r"((a)[3]), "r"((b)[0]), "r"((b)[1]))

#define STS128(addr, r0, r1, r2, r3) \
    asm volatile("st.shared.v4.b32 [%0], {%1,%2,%3,%4};" \
        :: "r"(addr), "r"(r0), "r"(r1), "r"(r2), "r"(r3) : "memory")

// ============================================================================
// Kernel 0a: transpose + hi/lo bf16 split: Wy[16384,1024] -> g_wt[1024][16384]
// ============================================================================
__global__ __launch_bounds__(256) void transpose_split(const float* __restrict__ Wy)
{
    __shared__ float T[32][33];
    const int k0 = blockIdx.x * 32;
    const int o0 = blockIdx.y * 32;
    const int tid = threadIdx.x;

    int r = tid >> 3, c4 = tid & 7;
    float4 v = *(const float4*)&Wy[(size_t)(k0 + r) * D_OUT + o0 + c4 * 4];
    T[r][c4 * 4 + 0] = v.x;  T[r][c4 * 4 + 1] = v.y;
    T[r][c4 * 4 + 2] = v.z;  T[r][c4 * 4 + 3] = v.w;
    __syncthreads();

    #pragma unroll
    for (int w = 0; w < 2; w++) {
        int idx = tid + w * 256;          // 0..511
        int o = idx >> 4, kp = (idx & 15) * 2;
        float a = T[kp][o], b = T[kp + 1][o];
        uint32_t h = pack_bf16(a, b);
        float fha = __uint_as_float(h << 16);
        float fhb = __uint_as_float(h & 0xFFFF0000u);
        uint32_t l = pack_bf16(a - fha, b - fhb);
        size_t dst = (size_t)(o0 + o) * KTOT + k0 + kp;
        *(uint32_t*)&g_wt_hi[dst] = h;
        *(uint32_t*)&g_wt_lo[dst] = l;
    }
}

// ============================================================================
// Kernel 0b: by[16][1024] -> g_by[1024][32] bf16 hi/lo (k 16..31 zero)
// ============================================================================
__global__ __launch_bounds__(256) void by_prep(const float* __restrict__ by)
{
    int o = blockIdx.x * 256 + threadIdx.x;
    if (o >= D_OUT) return;
    #pragma unroll
    for (int kp = 0; kp < 8; kp++) {
        float a = by[(size_t)(kp * 2)     * D_OUT + o];
        float b = by[(size_t)(kp * 2 + 1) * D_OUT + o];
        uint32_t h = pack_bf16(a, b);
        float fha = __uint_as_float(h << 16);
        float fhb = __uint_as_float(h & 0xFFFF0000u);
        uint32_t l = pack_bf16(a - fha, b - fhb);
        *(uint32_t*)&g_by_hi[(size_t)o * 32 + kp * 2] = h;
        *(uint32_t*)&g_by_lo[(size_t)o * 32 + kp * 2] = l;
    }
    #pragma unroll
    for (int kp = 8; kp < 16; kp++) {
        *(uint32_t*)&g_by_hi[(size_t)o * 32 + kp * 2] = 0u;
        *(uint32_t*)&g_by_lo[(size_t)o * 32 + kp * 2] = 0u;
    }
}

// ============================================================================
// Kernel 1: logits
// ============================================================================
__global__ __launch_bounds__(256) void logits_kernel(
    const float* __restrict__ x, const float* __restrict__ Wd,
    const float* __restrict__ bd)
{
    __shared__ float Xs[32][68];
    __shared__ float Ws[32][64];

    const int bm = blockIdx.y * 64;
    const int bc = blockIdx.x * 64;
    const int tid = threadIdx.x;
    const int tx = tid & 15, ty = tid >> 4;

    float acc[4][4] = {};

    for (int k0 = 0; k0 < D_IN; k0 += 32) {
        #pragma unroll
        for (int j = 0; j < 2; j++) {
            int L = tid + j * 256;
            int m = L >> 3, kq = L & 7;
            float4 v = *(const float4*)&x[(size_t)(bm + m) * D_IN + k0 + kq * 4];
            Xs[kq * 4 + 0][m] = v.x;  Xs[kq * 4 + 1][m] = v.y;
            Xs[kq * 4 + 2][m] = v.z;  Xs[kq * 4 + 3][m] = v.w;
        }
        #pragma unroll
        for (int j = 0; j < 2; j++) {
            int L = tid + j * 256;
            int kk = L >> 4, c4 = L & 15;
            int c = bc + c4 * 4;
            int n = c >> 4, jj = c & 15;
            float4 v = *(const float4*)&Wd[(size_t)n * (D_IN * N_CIT) + (size_t)(k0 + kk) * N_CIT + jj];
            *(float4*)&Ws[kk][c4 * 4] = v;
        }
        __syncthreads();
        #pragma unroll
        for (int kk = 0; kk < 32; kk++) {
            float4 a4 = *(const float4*)&Xs[kk][ty * 4];
            float4 b4 = *(const float4*)&Ws[kk][tx * 4];
            float a[4] = {a4.x, a4.y, a4.z, a4.w};
            float b[4] = {b4.x, b4.y, b4.z, b4.w};
            #pragma unroll
            for (int mi = 0; mi < 4; mi++)
                #pragma unroll
                for (int ci = 0; ci < 4; ci++)
                    acc[mi][ci] += a[mi] * b[ci];
        }
        __syncthreads();
    }

    const int cg = bc + tx * 4;
    #pragma unroll
    for (int mi = 0; mi < 4; mi++) {
        int m = bm + ty * 4 + mi;
        float4 r;
        r.x = acc[mi][0] + bd[cg + 0];
        r.y = acc[mi][1] + bd[cg + 1];
        r.z = acc[mi][2] + bd[cg + 2];
        r.w = acc[mi][3] + bd[cg + 3];
        *(float4*)&g_logits[(size_t)m * 256 + cg] = r;
    }
}

// ============================================================================
// Kernel 2: softmax + 16x16 solve -> power
// ============================================================================
__global__ __launch_bounds__(256) void power_kernel()
{
    int b = blockIdx.x * blockDim.x + threadIdx.x;
    if (b >= B_DIM) return;
    const float* lg = g_logits + (size_t)b * 256;
    const float ome = 1.f - EPSV;

    float A[16][17];
    float diag[16];

    #pragma unroll
    for (int n = 0; n < 16; n++) {
        float v[16];
        #pragma unroll
        for (int q = 0; q < 4; q++) {
            float4 t = *(const float4*)(lg + n * 16 + q * 4);
            v[q * 4 + 0] = t.x; v[q * 4 + 1] = t.y; v[q * 4 + 2] = t.z; v[q * 4 + 3] = t.w;
        }
        float mx = v[0];
        #pragma unroll
        for (int j = 1; j < 16; j++) mx = fmaxf(mx, v[j]);
        float s = 0.f;
        #pragma unroll
        for (int j = 0; j < 16; j++) { v[j] = expf(v[j] - mx); s += v[j]; }
        float inv = 1.f / s;
        #pragma unroll
        for (int j = 0; j < 16; j++) v[j] *= inv;
        diag[n] = v[n];
        #pragma unroll
        for (int r = 0; r < 16; r++) A[r][n] = (r == n) ? 1.f : -ome * v[r];
    }
    for (int r = 0; r < 16; r++) A[r][16] = 1.f;

    for (int p = 0; p < 16; p++) {
        float inv = 1.f / A[p][p];
        for (int c = p; c < 17; c++) A[p][c] *= inv;
        for (int r = p + 1; r < 16; r++) {
            float f = A[r][p];
            for (int c = p; c < 17; c++) A[r][c] -= f * A[p][c];
        }
    }
    float z[16];
    for (int r = 15; r >= 0; r--) {
        float s = A[r][16];
        for (int c = r + 1; c < 16; c++) s -= A[r][c] * z[c];
        z[r] = s;
    }
    float zs = 0.f;
    for (int i = 0; i < 16; i++) zs += z[i];
    float z16 = 1.f + EPSV * zs;
    float add = z16 * (1.f / 16.f) - (1.f / 16.f);
    for (int j = 0; j < 16; j++)
        g_power[(size_t)b * 16 + j] = z[j] * ome * diag[j] + add;
}

// ============================================================================
// Kernel 3: mma.sync split-bf16 GEMM. CTA tile 128x256, K-chunk 32, 2 buffers.
// SMEM buffer layout (stride 49152): A_hi[8K] A_lo[8K] B_hi[16K] B_lo[16K]
// Stages: 512 main (s = o*?; n = s&15, o = s>>4, k0 = n*1024 + o*32) + 1 bias.
// ============================================================================
#define BUFSTRIDE 49152
#define GSMEM_TOTAL (2 * BUFSTRIDE)

__device__ __forceinline__ void cp_b_stage(uint32_t buf, int bn, int t, int tid)
{
    uint32_t bh = buf + 16384, bl = buf + 32768;
    const char *sh, *sl;
    if (t < 512) {
        size_t off = ((size_t)(bn + tid) * KTOT +
                      (size_t)(t & 15) * 1024 + (size_t)(t >> 4) * 32) * 2;
        sh = (const char*)g_wt_hi + off;
        sl = (const char*)g_wt_lo + off;
    } else {
        size_t off = (size_t)(bn + tid) * 64;
        sh = (const char*)g_by_hi + off;
        sl = (const char*)g_by_lo + off;
    }
    #pragma unroll
    for (int q = 0; q < 4; q++) {
        CP_ASYNC16(sw(bh, tid, q), sh + q * 16);
        CP_ASYNC16(sw(bl, tid, q), sl + q * 16);
    }
}

__global__ __launch_bounds__(256, 1) void main_gemm(
    const float* __restrict__ x, float* __restrict__ out)
{
    extern __shared__ char smem[];
    const uint32_t sb = smem_to_u32(smem);
    const int tid = threadIdx.x;
    const int lane = tid & 31, w = tid >> 5;
    const int bm = blockIdx.y * 128;
    const int bn = blockIdx.x * 256;
    const int wm = (w & 1) * 64, wn = (w >> 1) * 64;

    float acc[4][8][4];
    #pragma unroll
    for (int t = 0; t < 4; t++)
        #pragma unroll
        for (int u = 0; u < 8; u++)
            #pragma unroll
            for (int c = 0; c < 4; c++) acc[t][u][c] = 0.f;

    // prologue: B of stage 0
    cp_b_stage(sb, bn, 0, tid);
    CP_COMMIT();

    const int ar = tid >> 1;           // A row this thread fills
    const int ah_half = tid & 1;       // which 16-k half

    const int j = lane >> 3, rr = lane & 7;   // ldmatrix lane decomposition

    for (int s = 0; s < 513; s++) {
        const uint32_t cb = sb + (uint32_t)(s & 1) * BUFSTRIDE;
        const uint32_t nb = sb + (uint32_t)((s + 1) & 1) * BUFSTRIDE;

        // ---- generate A tile (hi/lo) for this stage ----
        {
            float v[16];
            float p;
            if (s < 512) {
                const int n = s & 15, o = s >> 4;
                p = g_power[(size_t)(bm + ar) * 16 + n];
                const float* xp = x + (size_t)(bm + ar) * D_IN + o * 32 + ah_half * 16;
                #pragma unroll
                for (int q = 0; q < 4; q++) {
                    float4 t4 = *(const float4*)(xp + q * 4);
                    v[q * 4 + 0] = t4.x; v[q * 4 + 1] = t4.y;
                    v[q * 4 + 2] = t4.z; v[q * 4 + 3] = t4.w;
                }
            } else {
                p = 1.f;
                if (ah_half == 0) {
                    const float* pp = &g_power[(size_t)(bm + ar) * 16];
                    #pragma unroll
                    for (int q = 0; q < 4; q++) {
                        float4 t4 = *(const float4*)(pp + q * 4);
                        v[q * 4 + 0] = t4.x; v[q * 4 + 1] = t4.y;
                        v[q * 4 + 2] = t4.z; v[q * 4 + 3] = t4.w;
                    }
                } else {
                    #pragma unroll
                    for (int q = 0; q < 16; q++) v[q] = 0.f;
                }
            }
            #pragma unroll
            for (int q2 = 0; q2 < 2; q2++) {
                uint32_t hi4[4], lo4[4];
                #pragma unroll
                for (int i = 0; i < 4; i++) {
                    float f0 = v[q2 * 8 + i * 2]     * p;
                    float f1 = v[q2 * 8 + i * 2 + 1] * p;
                    uint32_t hb = pack_bf16(f0, f1);
                    float fh0 = __uint_as_float(hb << 16);
                    float fh1 = __uint_as_float(hb & 0xFFFF0000u);
                    hi4[i] = hb;
                    lo4[i] = pack_bf16(f0 - fh0, f1 - fh1);
                }
                int q = ah_half * 2 + q2;
                STS128(sw(cb, ar, q),        hi4[0], hi4[1], hi4[2], hi4[3]);
                STS128(sw(cb + 8192, ar, q), lo4[0], lo4[1], lo4[2], lo4[3]);
            }
        }

        // ---- prefetch next B, wait current B ----
        if (s + 1 < 513) {
            cp_b_stage(nb, bn, s + 1, tid);
            CP_COMMIT();
            CP_WAIT1();
        } else {
            CP_WAIT0();
        }
        __syncthreads();

        // ---- math: 2 x k16 steps ----
        #pragma unroll
        for (int kh = 0; kh < 2; kh++) {
            uint32_t afh[4][4], afl[4][4];
            #pragma unroll
            for (int t = 0; t < 4; t++) {
                int row = wm + t * 16 + ((j & 1) << 3) + rr;
                int q = kh * 2 + (j >> 1);
                LDSM4(afh[t], sw(cb, row, q));
                LDSM4(afl[t], sw(cb + 8192, row, q));
            }
            #pragma unroll
            for (int uh = 0; uh < 2; uh++) {
                uint32_t bfh[4][2], bfl[4][2];
                #pragma unroll
                for (int up = 0; up < 2; up++) {
                    int u0 = uh * 4 + up * 2;
                    int nrow = wn + u0 * 8 + ((j >> 1) << 3) + rr;
                    int q = kh * 2 + (j & 1);
                    uint32_t t4[4];
                    LDSM4(t4, sw(cb + 16384, nrow, q));
                    bfh[up * 2][0] = t4[0]; bfh[up * 2][1] = t4[1];
                    bfh[up * 2 + 1][0] = t4[2]; bfh[up * 2 + 1][1] = t4[3];
                    LDSM4(t4, sw(cb + 32768, nrow, q));
                    bfl[up * 2][0] = t4[0]; bfl[up * 2][1] = t4[1];
                    bfl[up * 2 + 1][0] = t4[2]; bfl[up * 2 + 1][1] = t4[3];
                }
                #pragma unroll
                for (int t = 0; t < 4; t++)
                    #pragma unroll
                    for (int uu = 0; uu < 4; uu++) {
                        MMA_BF16(acc[t][uh * 4 + uu], afh[t], bfh[uu]);
                        MMA_BF16(acc[t][uh * 4 + uu], afh[t], bfl[uu]);
                        MMA_BF16(acc[t][uh * 4 + uu], afl[t], bfh[uu]);
                    }
            }
        }
        __syncthreads();
    }

    // ---- epilogue: store accumulators ----
    #pragma unroll
    for (int t = 0; t < 4; t++) {
        int row0 = bm + wm + t * 16 + (lane >> 2);
        #pragma unroll
        for (int u = 0; u < 8; u++) {
            int col = bn + wn + u * 8 + (lane & 3) * 2;
            *(float2*)&out[(size_t)row0 * D_OUT + col] =
                make_float2(acc[t][u][0], acc[t][u][1]);
            *(float2*)&out[(size_t)(row0 + 8) * D_OUT + col] =
                make_float2(acc[t][u][2], acc[t][u][3]);
        }
    }
}

// ============================================================================
extern "C" void kernel_launch(void* const* d_in, const int* in_sizes, int n_in,
                              void* d_out, int out_size)
{
    const float* x  = (const float*)d_in[0];
    const float* Wy = (const float*)d_in[1];
    const float* by = (const float*)d_in[2];
    const float* Wd = (const float*)d_in[3];
    const float* bd = (const float*)d_in[4];
    float* out = (float*)d_out;

    cudaFuncSetAttribute(main_gemm, cudaFuncAttributeMaxDynamicSharedMemorySize,
                         GSMEM_TOTAL);

    transpose_split<<<dim3(KTOT / 32, D_OUT / 32), 256>>>(Wy);
    by_prep<<<D_OUT / 256, 256>>>(by);
    logits_kernel<<<dim3(256 / 64, B_DIM / 64), 256>>>(x, Wd, bd);
    power_kernel<<<B_DIM / 256, 256>>>();
    main_gemm<<<dim3(D_OUT / 256, B_DIM / 128), 256, GSMEM_TOTAL>>>(x, out);
}

// round 6
// speedup vs baseline: 2.7889x; 1.1294x over previous
#include <cuda_runtime.h>
#include <cuda_bf16.h>
#include <cstdint>

#define B_DIM 4096
#define N_CIT 16
#define D_IN  1024
#define D_OUT 1024
#define KTOT  (N_CIT * D_IN)       /* 16384 */
#define EPSV  0.01f

// ---------------- scratch (static device arrays; no cudaMalloc) -------------
__device__ float g_logits[B_DIM * 256];
__device__ float g_power [B_DIM * 16];
__device__ __nv_bfloat16 g_wt_hi[(size_t)D_OUT * KTOT];  // [o][k] K-major
__device__ __nv_bfloat16 g_wt_lo[(size_t)D_OUT * KTOT];
__device__ __nv_bfloat16 g_by_hi[(size_t)D_OUT * 32];    // [o][k] k=0..15 real, 16..31 zero
__device__ __nv_bfloat16 g_by_lo[(size_t)D_OUT * 32];

// ---------------- helpers ----------------------------------------------------
__device__ __forceinline__ uint32_t smem_to_u32(const void* p) {
    uint32_t a;
    asm("{ .reg .u64 t; cvta.to.shared.u64 t, %1; cvt.u32.u64 %0, t; }" : "=r"(a) : "l"(p));
    return a;
}

// swizzled address inside a tile of 64B rows: granule q (0..3) of row
__device__ __forceinline__ uint32_t sw(uint32_t base, int row, int q) {
    return base + row * 64 + (((uint32_t)(q ^ ((row >> 1) & 3))) << 4);
}

// pack two floats as bf16x2 (f0 -> low half)
__device__ __forceinline__ uint32_t pack_bf16(float f0, float f1) {
    uint32_t r;
    asm("cvt.rn.bf16x2.f32 %0, %1, %2;" : "=r"(r) : "f"(f1), "f"(f0));
    return r;
}

#define CP_ASYNC16(dst, src) \
    asm volatile("cp.async.cg.shared.global [%0], [%1], 16;" :: "r"(dst), "l"(src) : "memory")
#define CP_COMMIT() asm volatile("cp.async.commit_group;" ::: "memory")
#define CP_WAIT0()  asm volatile("cp.async.wait_group 0;" ::: "memory")

#define LDSM4(r, addr) \
    asm volatile("ldmatrix.sync.aligned.m8n8.x4.shared.b16 {%0,%1,%2,%3}, [%4];" \
        : "=r"((r)[0]), "=r"((r)[1]), "=r"((r)[2]), "=r"((r)[3]) : "r"(addr))

#define MMA_BF16(d, a, b) \
    asm volatile("mma.sync.aligned.m16n8k16.row.col.f32.bf16.bf16.f32 " \
        "{%0,%1,%2,%3}, {%4,%5,%6,%7}, {%8,%9}, {%0,%1,%2,%3};" \
        : "+f"((d)[0]), "+f"((d)[1]), "+f"((d)[2]), "+f"((d)[3]) \
        : "r"((a)[0]), "r"((a)[1]), "r"((a)[2]), "r"((a)[3]), "r"((b)[0]), "r"((b)[1]))

#define STS128(addr, r0, r1, r2, r3) \
    asm volatile("st.shared.v4.b32 [%0], {%1,%2,%3,%4};" \
        :: "r"(addr), "r"(r0), "r"(r1), "r"(r2), "r"(r3) : "memory")

// ============================================================================
// Kernel 0a: transpose + hi/lo bf16 split: Wy[16384,1024] -> g_wt[1024][16384]
// 64x64 tiles; reads and writes fully coalesced (128B warp segments).
// ============================================================================
__global__ __launch_bounds__(256) void transpose_split(const float* __restrict__ Wy)
{
    __shared__ float T[64][65];
    const int k0 = blockIdx.x * 64;
    const int o0 = blockIdx.y * 64;
    const int tid = threadIdx.x;

    // read 64k x 64o: 16 consecutive threads cover one row (256B)
    {
        int kr = tid >> 4, o4 = tid & 15;
        #pragma unroll
        for (int r = 0; r < 4; r++) {
            int k = kr + r * 16;
            float4 v = *(const float4*)&Wy[(size_t)(k0 + k) * D_OUT + o0 + o4 * 4];
            T[k][o4 * 4 + 0] = v.x;  T[k][o4 * 4 + 1] = v.y;
            T[k][o4 * 4 + 2] = v.z;  T[k][o4 * 4 + 3] = v.w;
        }
    }
    __syncthreads();

    // write: thread -> (o = tid>>2, kq = tid&3), 16 k values = 32B per array
    {
        int o = tid >> 2, kq = tid & 3;
        uint32_t hi[8], lo[8];
        #pragma unroll
        for (int i = 0; i < 8; i++) {
            float a = T[kq * 16 + i * 2][o];
            float b = T[kq * 16 + i * 2 + 1][o];
            uint32_t h = pack_bf16(a, b);
            float fha = __uint_as_float(h << 16);
            float fhb = __uint_as_float(h & 0xFFFF0000u);
            hi[i] = h;
            lo[i] = pack_bf16(a - fha, b - fhb);
        }
        size_t dst = (size_t)(o0 + o) * KTOT + k0 + kq * 16;
        *(uint4*)&g_wt_hi[dst]     = make_uint4(hi[0], hi[1], hi[2], hi[3]);
        *(uint4*)&g_wt_hi[dst + 8] = make_uint4(hi[4], hi[5], hi[6], hi[7]);
        *(uint4*)&g_wt_lo[dst]     = make_uint4(lo[0], lo[1], lo[2], lo[3]);
        *(uint4*)&g_wt_lo[dst + 8] = make_uint4(lo[4], lo[5], lo[6], lo[7]);
    }
}

// ============================================================================
// Kernel 0b: by[16][1024] -> g_by[1024][32] bf16 hi/lo (k 16..31 zero)
// ============================================================================
__global__ __launch_bounds__(256) void by_prep(const float* __restrict__ by)
{
    int o = blockIdx.x * 256 + threadIdx.x;
    if (o >= D_OUT) return;
    #pragma unroll
    for (int kp = 0; kp < 8; kp++) {
        float a = by[(size_t)(kp * 2)     * D_OUT + o];
        float b = by[(size_t)(kp * 2 + 1) * D_OUT + o];
        uint32_t h = pack_bf16(a, b);
        float fha = __uint_as_float(h << 16);
        float fhb = __uint_as_float(h & 0xFFFF0000u);
        uint32_t l = pack_bf16(a - fha, b - fhb);
        *(uint32_t*)&g_by_hi[(size_t)o * 32 + kp * 2] = h;
        *(uint32_t*)&g_by_lo[(size_t)o * 32 + kp * 2] = l;
    }
    #pragma unroll
    for (int kp = 8; kp < 16; kp++) {
        *(uint32_t*)&g_by_hi[(size_t)o * 32 + kp * 2] = 0u;
        *(uint32_t*)&g_by_lo[(size_t)o * 32 + kp * 2] = 0u;
    }
}

// ============================================================================
// Kernel 1: logits
// ============================================================================
__global__ __launch_bounds__(256) void logits_kernel(
    const float* __restrict__ x, const float* __restrict__ Wd,
    const float* __restrict__ bd)
{
    __shared__ float Xs[32][68];
    __shared__ float Ws[32][64];

    const int bm = blockIdx.y * 64;
    const int bc = blockIdx.x * 64;
    const int tid = threadIdx.x;
    const int tx = tid & 15, ty = tid >> 4;

    float acc[4][4] = {};

    for (int k0 = 0; k0 < D_IN; k0 += 32) {
        #pragma unroll
        for (int j = 0; j < 2; j++) {
            int L = tid + j * 256;
            int m = L >> 3, kq = L & 7;
            float4 v = *(const float4*)&x[(size_t)(bm + m) * D_IN + k0 + kq * 4];
            Xs[kq * 4 + 0][m] = v.x;  Xs[kq * 4 + 1][m] = v.y;
            Xs[kq * 4 + 2][m] = v.z;  Xs[kq * 4 + 3][m] = v.w;
        }
        #pragma unroll
        for (int j = 0; j < 2; j++) {
            int L = tid + j * 256;
            int kk = L >> 4, c4 = L & 15;
            int c = bc + c4 * 4;
            int n = c >> 4, jj = c & 15;
            float4 v = *(const float4*)&Wd[(size_t)n * (D_IN * N_CIT) + (size_t)(k0 + kk) * N_CIT + jj];
            *(float4*)&Ws[kk][c4 * 4] = v;
        }
        __syncthreads();
        #pragma unroll
        for (int kk = 0; kk < 32; kk++) {
            float4 a4 = *(const float4*)&Xs[kk][ty * 4];
            float4 b4 = *(const float4*)&Ws[kk][tx * 4];
            float a[4] = {a4.x, a4.y, a4.z, a4.w};
            float b[4] = {b4.x, b4.y, b4.z, b4.w};
            #pragma unroll
            for (int mi = 0; mi < 4; mi++)
                #pragma unroll
                for (int ci = 0; ci < 4; ci++)
                    acc[mi][ci] += a[mi] * b[ci];
        }
        __syncthreads();
    }

    const int cg = bc + tx * 4;
    #pragma unroll
    for (int mi = 0; mi < 4; mi++) {
        int m = bm + ty * 4 + mi;
        float4 r;
        r.x = acc[mi][0] + bd[cg + 0];
        r.y = acc[mi][1] + bd[cg + 1];
        r.z = acc[mi][2] + bd[cg + 2];
        r.w = acc[mi][3] + bd[cg + 3];
        *(float4*)&g_logits[(size_t)m * 256 + cg] = r;
    }
}

// ============================================================================
// Kernel 2: softmax + 16x16 solve -> power.  32-thread blocks spread over SMs.
// ============================================================================
__global__ __launch_bounds__(32) void power_kernel()
{
    int b = blockIdx.x * 32 + threadIdx.x;
    if (b >= B_DIM) return;
    const float* lg = g_logits + (size_t)b * 256;
    const float ome = 1.f - EPSV;

    float A[16][17];
    float diag[16];

    #pragma unroll
    for (int n = 0; n < 16; n++) {
        float v[16];
        #pragma unroll
        for (int q = 0; q < 4; q++) {
            float4 t = *(const float4*)(lg + n * 16 + q * 4);
            v[q * 4 + 0] = t.x; v[q * 4 + 1] = t.y; v[q * 4 + 2] = t.z; v[q * 4 + 3] = t.w;
        }
        float mx = v[0];
        #pragma unroll
        for (int j = 1; j < 16; j++) mx = fmaxf(mx, v[j]);
        float s = 0.f;
        #pragma unroll
        for (int j = 0; j < 16; j++) { v[j] = expf(v[j] - mx); s += v[j]; }
        float inv = 1.f / s;
        #pragma unroll
        for (int j = 0; j < 16; j++) v[j] *= inv;
        diag[n] = v[n];
        #pragma unroll
        for (int r = 0; r < 16; r++) A[r][n] = (r == n) ? 1.f : -ome * v[r];
    }
    for (int r = 0; r < 16; r++) A[r][16] = 1.f;

    for (int p = 0; p < 16; p++) {
        float inv = 1.f / A[p][p];
        for (int c = p; c < 17; c++) A[p][c] *= inv;
        for (int r = p + 1; r < 16; r++) {
            float f = A[r][p];
            for (int c = p; c < 17; c++) A[r][c] -= f * A[p][c];
        }
    }
    float z[16];
    for (int r = 15; r >= 0; r--) {
        float s = A[r][16];
        for (int c = r + 1; c < 16; c++) s -= A[r][c] * z[c];
        z[r] = s;
    }
    float zs = 0.f;
    for (int i = 0; i < 16; i++) zs += z[i];
    float z16 = 1.f + EPSV * zs;
    float add = z16 * (1.f / 16.f) - (1.f / 16.f);
    for (int j = 0; j < 16; j++)
        g_power[(size_t)b * 16 + j] = z[j] * ome * diag[j] + add;
}

// ============================================================================
// Kernel 3: mma.sync split-bf16 GEMM. CTA tile 128x256, K-chunk 32, 2 buffers.
// SMEM buffer (stride 49152): A_hi[8K] A_lo[8K] B_hi[16K] B_lo[16K]
// Single sync per stage; A-gen for s+1 interleaved between the k16 halves.
// ============================================================================
#define BUFSTRIDE 49152
#define GSMEM_TOTAL (2 * BUFSTRIDE)
#define NSTG 513

__device__ __forceinline__ void cp_b_stage(uint32_t buf, int bn, int t, int tid)
{
    uint32_t bh = buf + 16384, bl = buf + 32768;
    const char *sh, *sl;
    if (t < 512) {
        size_t off = ((size_t)(bn + tid) * KTOT +
                      (size_t)(t & 15) * 1024 + (size_t)(t >> 4) * 32) * 2;
        sh = (const char*)g_wt_hi + off;
        sl = (const char*)g_wt_lo + off;
    } else {
        size_t off = (size_t)(bn + tid) * 64;
        sh = (const char*)g_by_hi + off;
        sl = (const char*)g_by_lo + off;
    }
    #pragma unroll
    for (int q = 0; q < 4; q++) {
        CP_ASYNC16(sw(bh, tid, q), sh + q * 16);
        CP_ASYNC16(sw(bl, tid, q), sl + q * 16);
    }
}

// generate the A tile (hi/lo split of power-scaled x) for stage t into buf
__device__ __forceinline__ void gen_a_stage(uint32_t buf, const float* __restrict__ x,
                                            int bm, int t, int tid)
{
    const int ar = tid >> 1;
    const int ah_half = tid & 1;
    float v[16];
    float p;
    if (t < 512) {
        const int n = t & 15, o = t >> 4;
        p = g_power[(size_t)(bm + ar) * 16 + n];
        const float* xp = x + (size_t)(bm + ar) * D_IN + o * 32 + ah_half * 16;
        #pragma unroll
        for (int q = 0; q < 4; q++) {
            float4 t4 = *(const float4*)(xp + q * 4);
            v[q * 4 + 0] = t4.x; v[q * 4 + 1] = t4.y;
            v[q * 4 + 2] = t4.z; v[q * 4 + 3] = t4.w;
        }
    } else {
        p = 1.f;
        if (ah_half == 0) {
            const float* pp = &g_power[(size_t)(bm + ar) * 16];
            #pragma unroll
            for (int q = 0; q < 4; q++) {
                float4 t4 = *(const float4*)(pp + q * 4);
                v[q * 4 + 0] = t4.x; v[q * 4 + 1] = t4.y;
                v[q * 4 + 2] = t4.z; v[q * 4 + 3] = t4.w;
            }
        } else {
            #pragma unroll
            for (int q = 0; q < 16; q++) v[q] = 0.f;
        }
    }
    #pragma unroll
    for (int q2 = 0; q2 < 2; q2++) {
        uint32_t hi4[4], lo4[4];
        #pragma unroll
        for (int i = 0; i < 4; i++) {
            float f0 = v[q2 * 8 + i * 2]     * p;
            float f1 = v[q2 * 8 + i * 2 + 1] * p;
            uint32_t hb = pack_bf16(f0, f1);
            float fh0 = __uint_as_float(hb << 16);
            float fh1 = __uint_as_float(hb & 0xFFFF0000u);
            hi4[i] = hb;
            lo4[i] = pack_bf16(f0 - fh0, f1 - fh1);
        }
        int q = ah_half * 2 + q2;
        STS128(sw(buf, ar, q),        hi4[0], hi4[1], hi4[2], hi4[3]);
        STS128(sw(buf + 8192, ar, q), lo4[0], lo4[1], lo4[2], lo4[3]);
    }
}

__global__ __launch_bounds__(256, 1) void main_gemm(
    const float* __restrict__ x, float* __restrict__ out)
{
    extern __shared__ char smem[];
    const uint32_t sb = smem_to_u32(smem);
    const int tid = threadIdx.x;
    const int lane = tid & 31, w = tid >> 5;
    const int bm = blockIdx.y * 128;
    const int bn = blockIdx.x * 256;
    const int wm = (w & 1) * 64, wn = (w >> 1) * 64;

    float acc[4][8][4];
    #pragma unroll
    for (int t = 0; t < 4; t++)
        #pragma unroll
        for (int u = 0; u < 8; u++)
            #pragma unroll
            for (int c = 0; c < 4; c++) acc[t][u][c] = 0.f;

    // prologue: stage 0 into buffer 0
    cp_b_stage(sb, bn, 0, tid);
    CP_COMMIT();
    gen_a_stage(sb, x, bm, 0, tid);
    CP_WAIT0();
    __syncthreads();

    const int j = lane >> 3, rr = lane & 7;   // ldmatrix lane decomposition

    for (int s = 0; s < NSTG; s++) {
        const uint32_t cb = sb + (uint32_t)(s & 1) * BUFSTRIDE;
        const uint32_t nb = sb + (uint32_t)((s + 1) & 1) * BUFSTRIDE;
        const bool has_next = (s + 1 < NSTG);

        // prefetch next B early
        if (has_next) {
            cp_b_stage(nb, bn, s + 1, tid);
            CP_COMMIT();
        }

        // ---- math kh = 0 ----
        {
            const int kh = 0;
            uint32_t afh[4][4], afl[4][4];
            #pragma unroll
            for (int t = 0; t < 4; t++) {
                int row = wm + t * 16 + ((j & 1) << 3) + rr;
                int q = kh * 2 + (j >> 1);
                LDSM4(afh[t], sw(cb, row, q));
                LDSM4(afl[t], sw(cb + 8192, row, q));
            }
            #pragma unroll
            for (int uh = 0; uh < 2; uh++) {
                uint32_t bfh[4][2], bfl[4][2];
                #pragma unroll
                for (int up = 0; up < 2; up++) {
                    int u0 = uh * 4 + up * 2;
                    int nrow = wn + u0 * 8 + ((j >> 1) << 3) + rr;
                    int q = kh * 2 + (j & 1);
                    uint32_t t4[4];
                    LDSM4(t4, sw(cb + 16384, nrow, q));
                    bfh[up * 2][0] = t4[0]; bfh[up * 2][1] = t4[1];
                    bfh[up * 2 + 1][0] = t4[2]; bfh[up * 2 + 1][1] = t4[3];
                    LDSM4(t4, sw(cb + 32768, nrow, q));
                    bfl[up * 2][0] = t4[0]; bfl[up * 2][1] = t4[1];
                    bfl[up * 2 + 1][0] = t4[2]; bfl[up * 2 + 1][1] = t4[3];
                }
                #pragma unroll
                for (int t = 0; t < 4; t++)
                    #pragma unroll
                    for (int uu = 0; uu < 4; uu++) {
                        MMA_BF16(acc[t][uh * 4 + uu], afh[t], bfh[uu]);
                        MMA_BF16(acc[t][uh * 4 + uu], afh[t], bfl[uu]);
                        MMA_BF16(acc[t][uh * 4 + uu], afl[t], bfh[uu]);
                    }
            }
        }

        // ---- generate A for stage s+1 (hidden under kh=0 HMMA backlog) ----
        if (has_next)
            gen_a_stage(nb, x, bm, s + 1, tid);

        // ---- math kh = 1 ----
        {
            const int kh = 1;
            uint32_t afh[4][4], afl[4][4];
            #pragma unroll
            for (int t = 0; t < 4; t++) {
                int row = wm + t * 16 + ((j & 1) << 3) + rr;
                int q = kh * 2 + (j >> 1);
                LDSM4(afh[t], sw(cb, row, q));
                LDSM4(afl[t], sw(cb + 8192, row, q));
            }
            #pragma unroll
            for (int uh = 0; uh < 2; uh++) {
                uint32_t bfh[4][2], bfl[4][2];
                #pragma unroll
                for (int up = 0; up < 2; up++) {
                    int u0 = uh * 4 + up * 2;
                    int nrow = wn + u0 * 8 + ((j >> 1) << 3) + rr;
                    int q = kh * 2 + (j & 1);
                    uint32_t t4[4];
                    LDSM4(t4, sw(cb + 16384, nrow, q));
                    bfh[up * 2][0] = t4[0]; bfh[up * 2][1] = t4[1];
                    bfh[up * 2 + 1][0] = t4[2]; bfh[up * 2 + 1][1] = t4[3];
                    LDSM4(t4, sw(cb + 32768, nrow, q));
                    bfl[up * 2][0] = t4[0]; bfl[up * 2][1] = t4[1];
                    bfl[up * 2 + 1][0] = t4[2]; bfl[up * 2 + 1][1] = t4[3];
                }
                #pragma unroll
                for (int t = 0; t < 4; t++)
                    #pragma unroll
                    for (int uu = 0; uu < 4; uu++) {
                        MMA_BF16(acc[t][uh * 4 + uu], afh[t], bfh[uu]);
                        MMA_BF16(acc[t][uh * 4 + uu], afh[t], bfl[uu]);
                        MMA_BF16(acc[t][uh * 4 + uu], afl[t], bfh[uu]);
                    }
            }
        }

        if (has_next) CP_WAIT0();
        __syncthreads();
    }

    // ---- epilogue: store accumulators ----
    #pragma unroll
    for (int t = 0; t < 4; t++) {
        int row0 = bm + wm + t * 16 + (lane >> 2);
        #pragma unroll
        for (int u = 0; u < 8; u++) {
            int col = bn + wn + u * 8 + (lane & 3) * 2;
            *(float2*)&out[(size_t)row0 * D_OUT + col] =
                make_float2(acc[t][u][0], acc[t][u][1]);
            *(float2*)&out[(size_t)(row0 + 8) * D_OUT + col] =
                make_float2(acc[t][u][2], acc[t][u][3]);
        }
    }
}

// ============================================================================
extern "C" void kernel_launch(void* const* d_in, const int* in_sizes, int n_in,
                              void* d_out, int out_size)
{
    const float* x  = (const float*)d_in[0];
    const float* Wy = (const float*)d_in[1];
    const float* by = (const float*)d_in[2];
    const float* Wd = (const float*)d_in[3];
    const float* bd = (const float*)d_in[4];
    float* out = (float*)d_out;

    cudaFuncSetAttribute(main_gemm, cudaFuncAttributeMaxDynamicSharedMemorySize,
                         GSMEM_TOTAL);

    transpose_split<<<dim3(KTOT / 64, D_OUT / 64), 256>>>(Wy);
    by_prep<<<D_OUT / 256, 256>>>(by);
    logits_kernel<<<dim3(256 / 64, B_DIM / 64), 256>>>(x, Wd, bd);
    power_kernel<<<B_DIM / 32, 32>>>();
    main_gemm<<<dim3(D_OUT / 256, B_DIM / 128), 256, GSMEM_TOTAL>>>(x, out);
}